// round 2
// baseline (speedup 1.0000x reference)
#include <cuda_runtime.h>
#include <math.h>

// Problem constants
#define BATCH  4
#define SEQ    1024
#define CDIM   1024
#define HEADS  16
#define DHEAD  64
#define CHUNK  64
#define NCHUNK 16
#define TOPKN  32
#define SCALEF 0.125f   // 1/sqrt(64)

// Scratch (allocation-free rule: device globals)
__device__ float g_q[BATCH*SEQ*CDIM];
__device__ float g_k[BATCH*SEQ*CDIM];
__device__ float g_v[BATCH*SEQ*CDIM];
__device__ float g_attn[BATCH*SEQ*CDIM];

// ---------------------------------------------------------------------------
// Tiled FP32 GEMM: C[M,N] = A[M,K] @ B[K,N], all row-major.
// BM=BN=128, BK=8, 256 threads, 8x8 per thread.
// ---------------------------------------------------------------------------
#define GBM 128
#define GBN 128
#define GBK 8

__global__ __launch_bounds__(256)
void sgemm_kernel(const float* __restrict__ A, const float* __restrict__ B,
                  float* __restrict__ C, int M, int N, int K)
{
    __shared__ float As[GBK][GBM];
    __shared__ float Bs[GBK][GBN];

    const int tid = threadIdx.x;
    const int bx = blockIdx.x, by = blockIdx.y;

    const int a_r = tid >> 1;            // 0..127
    const int a_c = (tid & 1) * 4;       // 0 or 4
    const int b_r = tid >> 5;            // 0..7
    const int b_c = (tid & 31) * 4;      // 0..124

    const float* Ab = A + (size_t)(by * GBM) * K;
    const float* Bb = B + bx * GBN;

    const int tx = tid & 15;             // 0..15
    const int ty = tid >> 4;             // 0..15

    float acc[8][8];
#pragma unroll
    for (int i = 0; i < 8; i++)
#pragma unroll
        for (int j = 0; j < 8; j++) acc[i][j] = 0.f;

    for (int k0 = 0; k0 < K; k0 += GBK) {
        float4 av = *(const float4*)(Ab + (size_t)a_r * K + k0 + a_c);
        As[a_c + 0][a_r] = av.x;
        As[a_c + 1][a_r] = av.y;
        As[a_c + 2][a_r] = av.z;
        As[a_c + 3][a_r] = av.w;
        float4 bv = *(const float4*)(Bb + (size_t)(k0 + b_r) * N + b_c);
        *(float4*)&Bs[b_r][b_c] = bv;
        __syncthreads();

#pragma unroll
        for (int kk = 0; kk < GBK; kk++) {
            float ar[8], br[8];
#pragma unroll
            for (int i = 0; i < 8; i++) ar[i] = As[kk][ty * 8 + i];
#pragma unroll
            for (int j = 0; j < 8; j++) br[j] = Bs[kk][tx * 8 + j];
#pragma unroll
            for (int i = 0; i < 8; i++)
#pragma unroll
                for (int j = 0; j < 8; j++)
                    acc[i][j] = fmaf(ar[i], br[j], acc[i][j]);
        }
        __syncthreads();
    }

#pragma unroll
    for (int i = 0; i < 8; i++) {
        float* crow = C + (size_t)(by * GBM + ty * 8 + i) * N + bx * GBN + tx * 8;
#pragma unroll
        for (int j = 0; j < 8; j += 4) {
            float4 o = make_float4(acc[i][j], acc[i][j+1], acc[i][j+2], acc[i][j+3]);
            *(float4*)(crow + j) = o;
        }
    }
}

// ---------------------------------------------------------------------------
// Sparse chunked attention.
// Grid: (SEQ/32, HEADS, BATCH); 256 threads (8 warps); warp handles 4 queries.
// Per chunk of 64 keys: scores (2 keys/lane), exact 32nd-largest via radix
// select on order-preserving uint map, zero below threshold, softmax over all
// 64 entries (zeros included), p@v accumulate. Output /= 16 (the normalizer).
// ---------------------------------------------------------------------------
#define QB 32

__device__ __forceinline__ unsigned f2u(float f) {
    unsigned b = __float_as_uint(f);
    return (b & 0x80000000u) ? ~b : (b | 0x80000000u);
}
__device__ __forceinline__ float u2f(unsigned u) {
    unsigned b = (u & 0x80000000u) ? (u & 0x7fffffffu) : ~u;
    return __uint_as_float(b);
}

__global__ __launch_bounds__(256)
void attn_kernel(const float* __restrict__ q, const float* __restrict__ k,
                 const float* __restrict__ v, const float* __restrict__ imp,
                 const float* __restrict__ temps, float* __restrict__ out)
{
    __shared__ float q_s[QB][DHEAD];          // 8 KB
    __shared__ float kT[DHEAD][CHUNK + 1];    // 16.25 KB (transposed, padded)
    __shared__ float v_s[CHUNK][DHEAD];       // 16 KB
    __shared__ float fac_s[QB];

    const int b  = blockIdx.z;
    const int h  = blockIdx.y;
    const int t0 = blockIdx.x * QB;
    const int tid  = threadIdx.x;
    const int lane = tid & 31;
    const int wid  = tid >> 5;

    // per-query score factor: SCALE / clip(temp) * sigmoid((sigmoid(imp)-0.5)*10)
    if (tid < QB) {
        float tmp = temps[b * HEADS + h];
        tmp = fminf(fmaxf(tmp, 0.1f), 100.f);
        float is = imp[((size_t)b * SEQ + (t0 + tid)) * HEADS + h];
        float ip = 1.f / (1.f + expf(-is));
        float mw = 1.f / (1.f + expf(-((ip - 0.5f) * 10.f)));
        fac_s[tid] = (SCALEF / tmp) * mw;
    }

    // load 32 queries
    for (int i = tid; i < QB * DHEAD / 4; i += 256) {
        int qq = i / (DHEAD / 4);
        int dd = (i % (DHEAD / 4)) * 4;
        *(float4*)&q_s[qq][dd] =
            *(const float4*)&q[((size_t)b * SEQ + (t0 + qq)) * CDIM + h * DHEAD + dd];
    }

    float acc0[4] = {0.f, 0.f, 0.f, 0.f};
    float acc1[4] = {0.f, 0.f, 0.f, 0.f};
    const int d0 = lane * 2;
    const int qbase = wid * 4;

    for (int ck = 0; ck < NCHUNK; ck++) {
        __syncthreads();   // also protects q_s/fac_s on first iter, reuse after
        const int kt0 = ck * CHUNK;
        for (int i = tid; i < CHUNK * DHEAD / 4; i += 256) {
            int j  = i / (DHEAD / 4);
            int dd = (i % (DHEAD / 4)) * 4;
            size_t gidx = ((size_t)b * SEQ + (kt0 + j)) * CDIM + h * DHEAD + dd;
            float4 kv = *(const float4*)&k[gidx];
            kT[dd + 0][j] = kv.x;
            kT[dd + 1][j] = kv.y;
            kT[dd + 2][j] = kv.z;
            kT[dd + 3][j] = kv.w;
            *(float4*)&v_s[j][dd] = *(const float4*)&v[gidx];
        }
        __syncthreads();

        // scores for 4 queries x (2 keys per lane)
        float s0[4] = {0.f, 0.f, 0.f, 0.f};
        float s1[4] = {0.f, 0.f, 0.f, 0.f};
#pragma unroll 8
        for (int d = 0; d < DHEAD; d++) {
            float k0v = kT[d][lane];
            float k1v = kT[d][lane + 32];
#pragma unroll
            for (int qi = 0; qi < 4; qi++) {
                float qd = q_s[qbase + qi][d];
                s0[qi] = fmaf(qd, k0v, s0[qi]);
                s1[qi] = fmaf(qd, k1v, s1[qi]);
            }
        }

#pragma unroll 1
        for (int qi = 0; qi < 4; qi++) {
            float f  = fac_s[qbase + qi];
            float a0 = s0[qi] * f;
            float a1 = s1[qi] * f;

            // exact 32nd-largest of 64 via MSB-first radix select
            unsigned u0 = f2u(a0), u1 = f2u(a1);
            unsigned prefix = 0;
            int kk = TOPKN;
#pragma unroll 1
            for (int bit = 31; bit >= 0; --bit) {
                unsigned bm = 1u << bit;
                unsigned hm = ~((bm << 1) - 1u);   // bits above 'bit' (0 when bit==31)
                int c0 = (((u0 & hm) == prefix) && (u0 & bm)) ? 1 : 0;
                int c1 = (((u1 & hm) == prefix) && (u1 & bm)) ? 1 : 0;
                int cnt = __popc(__ballot_sync(0xffffffffu, c0)) +
                          __popc(__ballot_sync(0xffffffffu, c1));
                if (cnt >= kk) prefix |= bm;
                else           kk -= cnt;
            }
            float thr = u2f(prefix);

            float m0 = (a0 >= thr) ? a0 : 0.f;
            float m1 = (a1 >= thr) ? a1 : 0.f;
            float mx = fmaxf(m0, m1);
#pragma unroll
            for (int o = 16; o; o >>= 1)
                mx = fmaxf(mx, __shfl_xor_sync(0xffffffffu, mx, o));
            float e0 = expf(m0 - mx);
            float e1 = expf(m1 - mx);
            float ds = e0 + e1;
#pragma unroll
            for (int o = 16; o; o >>= 1)
                ds += __shfl_xor_sync(0xffffffffu, ds, o);
            float inv = 1.f / ds;
            float p0 = e0 * inv;
            float p1 = e1 * inv;

            // p @ v  (broadcast p via shfl; lane owns out dims d0,d0+1)
            float a_x = acc0[qi], a_y = acc1[qi];
#pragma unroll
            for (int j = 0; j < 32; j++) {
                float pj = __shfl_sync(0xffffffffu, p0, j);
                float2 vv = *(const float2*)&v_s[j][d0];
                a_x = fmaf(pj, vv.x, a_x);
                a_y = fmaf(pj, vv.y, a_y);
            }
#pragma unroll
            for (int j = 0; j < 32; j++) {
                float pj = __shfl_sync(0xffffffffu, p1, j);
                float2 vv = *(const float2*)&v_s[j + 32][d0];
                a_x = fmaf(pj, vv.x, a_x);
                a_y = fmaf(pj, vv.y, a_y);
            }
            acc0[qi] = a_x; acc1[qi] = a_y;
        }
    }

    // write [B,T,C] layout, divided by normalizer (= NCHUNK = 16 exactly)
    const float invn = 1.f / 16.f;
#pragma unroll
    for (int qi = 0; qi < 4; qi++) {
        int ql = qbase + qi;
        float2 o2 = make_float2(acc0[qi] * invn, acc1[qi] * invn);
        *(float2*)&out[((size_t)b * SEQ + (t0 + ql)) * CDIM + h * DHEAD + d0] = o2;
    }
}

// ---------------------------------------------------------------------------
// Launch
// ---------------------------------------------------------------------------
extern "C" void kernel_launch(void* const* d_in, const int* in_sizes, int n_in,
                              void* d_out, int out_size)
{
    const float* x    = (const float*)d_in[0];
    const float* impS = (const float*)d_in[1];
    const float* temp = (const float*)d_in[2];
    const float* Wq   = (const float*)d_in[3];
    const float* Wk   = (const float*)d_in[4];
    const float* Wv   = (const float*)d_in[5];
    const float* Wo   = (const float*)d_in[6];
    float* outp = (float*)d_out;

    float *pq, *pk, *pv, *pa;
    cudaGetSymbolAddress((void**)&pq, g_q);
    cudaGetSymbolAddress((void**)&pk, g_k);
    cudaGetSymbolAddress((void**)&pv, g_v);
    cudaGetSymbolAddress((void**)&pa, g_attn);

    const int M = BATCH * SEQ;   // 4096
    const int N = CDIM;          // 1024
    const int K = CDIM;          // 1024
    dim3 ggrid(N / GBN, M / GBM);

    sgemm_kernel<<<ggrid, 256>>>(x, Wq, pq, M, N, K);
    sgemm_kernel<<<ggrid, 256>>>(x, Wk, pk, M, N, K);
    sgemm_kernel<<<ggrid, 256>>>(x, Wv, pv, M, N, K);

    dim3 agrid(SEQ / QB, HEADS, BATCH);
    attn_kernel<<<agrid, 256>>>(pq, pk, pv, impS, temp, pa);

    sgemm_kernel<<<ggrid, 256>>>(pa, Wo, outp, M, N, K);
}

// round 4
// speedup vs baseline: 1.3335x; 1.3335x over previous
#include <cuda_runtime.h>
#include <math.h>

typedef unsigned long long ull;

// Problem constants
#define BATCH  4
#define SEQ    1024
#define CDIM   1024
#define HEADS  16
#define DHEAD  64
#define CHUNK  64
#define NCHUNK 16
#define TOPKN  32
#define SCALEF 0.125f   // 1/sqrt(64)

// Scratch (allocation-free rule: device globals)
__device__ float g_q[BATCH*SEQ*CDIM];
__device__ float g_k[BATCH*SEQ*CDIM];
__device__ float g_v[BATCH*SEQ*CDIM];
__device__ float g_attn[BATCH*SEQ*CDIM];

// ---------------- f32x2 packed helpers (Blackwell FFMA2 path) --------------
__device__ __forceinline__ ull pack2(float lo, float hi) {
    ull r; asm("mov.b64 %0, {%1, %2};" : "=l"(r) : "f"(lo), "f"(hi)); return r;
}
__device__ __forceinline__ float lo2(ull v) {
    float a, b; asm("mov.b64 {%0, %1}, %2;" : "=f"(a), "=f"(b) : "l"(v)); return a;
}
__device__ __forceinline__ float hi2(ull v) {
    float a, b; asm("mov.b64 {%0, %1}, %2;" : "=f"(a), "=f"(b) : "l"(v)); return b;
}
__device__ __forceinline__ ull ffma2(ull a, ull b, ull c) {
    ull d; asm("fma.rn.f32x2 %0, %1, %2, %3;" : "=l"(d) : "l"(a), "l"(b), "l"(c));
    return d;
}

// ---------------------------------------------------------------------------
// Tiled FP32 GEMM with packed f32x2 FMA: C[M,N] = A[M,K] @ B[K,N], row-major.
// BM=BN=128, BK=16, 256 threads, 8x8 per thread (row-pairs packed in f32x2).
// ---------------------------------------------------------------------------
#define GBM 128
#define GBN 128
#define GBK 16

__global__ __launch_bounds__(256)
void sgemm_kernel(const float* __restrict__ A, const float* __restrict__ B,
                  float* __restrict__ C, int M, int N, int K)
{
    __shared__ float As[GBK][GBM];   // transposed A tile
    __shared__ float Bs[GBK][GBN];

    const int tid = threadIdx.x;
    const int bx = blockIdx.x, by = blockIdx.y;

    const int a_r = tid >> 1;            // 0..127
    const int a_c = (tid & 1) * 8;       // 0 or 8
    const int b_r = tid >> 5;            // 0..7 (loads rows b_r and b_r+8)
    const int b_c = (tid & 31) * 4;      // 0..124

    const float* Ab = A + (size_t)(by * GBM) * K;
    const float* Bb = B + bx * GBN;

    const int tx = tid & 15;             // 0..15
    const int ty = tid >> 4;             // 0..15

    ull acc2[4][8];                      // row-pair x col, packed f32x2
#pragma unroll
    for (int i = 0; i < 4; i++)
#pragma unroll
        for (int j = 0; j < 8; j++) acc2[i][j] = 0ull;

    for (int k0 = 0; k0 < K; k0 += GBK) {
        float4 av0 = *(const float4*)(Ab + (size_t)a_r * K + k0 + a_c);
        float4 av1 = *(const float4*)(Ab + (size_t)a_r * K + k0 + a_c + 4);
        As[a_c + 0][a_r] = av0.x; As[a_c + 1][a_r] = av0.y;
        As[a_c + 2][a_r] = av0.z; As[a_c + 3][a_r] = av0.w;
        As[a_c + 4][a_r] = av1.x; As[a_c + 5][a_r] = av1.y;
        As[a_c + 6][a_r] = av1.z; As[a_c + 7][a_r] = av1.w;
        *(float4*)&Bs[b_r][b_c]     = *(const float4*)(Bb + (size_t)(k0 + b_r) * N + b_c);
        *(float4*)&Bs[b_r + 8][b_c] = *(const float4*)(Bb + (size_t)(k0 + b_r + 8) * N + b_c);
        __syncthreads();

#pragma unroll
        for (int kk = 0; kk < GBK; kk++) {
            ull ar2[4];
#pragma unroll
            for (int ip = 0; ip < 4; ip++)
                ar2[ip] = *(const ull*)&As[kk][ty * 8 + 2 * ip];
#pragma unroll
            for (int j = 0; j < 8; j++) {
                float bv = Bs[kk][tx * 8 + j];
                ull bd = pack2(bv, bv);
#pragma unroll
                for (int ip = 0; ip < 4; ip++)
                    acc2[ip][j] = ffma2(ar2[ip], bd, acc2[ip][j]);
            }
        }
        __syncthreads();
    }

#pragma unroll
    for (int ip = 0; ip < 4; ip++) {
        float r0[8], r1[8];
#pragma unroll
        for (int j = 0; j < 8; j++) { r0[j] = lo2(acc2[ip][j]); r1[j] = hi2(acc2[ip][j]); }
        float* c0 = C + (size_t)(by * GBM + ty * 8 + 2 * ip) * N + bx * GBN + tx * 8;
        float* c1 = c0 + N;
        *(float4*)(c0 + 0) = make_float4(r0[0], r0[1], r0[2], r0[3]);
        *(float4*)(c0 + 4) = make_float4(r0[4], r0[5], r0[6], r0[7]);
        *(float4*)(c1 + 0) = make_float4(r1[0], r1[1], r1[2], r1[3]);
        *(float4*)(c1 + 4) = make_float4(r1[4], r1[5], r1[6], r1[7]);
    }
}

// ---------------------------------------------------------------------------
// Sparse chunked attention.
// Grid: (SEQ/32, HEADS, BATCH); 256 threads (8 warps); warp handles 4 queries.
// Per chunk of 64 keys: scores via packed f32x2 FMA (2 keys/lane), exact
// 32nd-largest via warp bitonic sort of 64 values (2/lane), zero below
// threshold, softmax over all 64 entries (zeros included), p@v accumulate.
// Output /= 16 (the normalizer sum(p) is exactly NCHUNK).
// ---------------------------------------------------------------------------
#define QB 32

// bitonic compare-exchange step via shfl (ascending overall sort)
__device__ __forceinline__ void bcas(float& x, int i, int j, int k) {
    float pv = __shfl_xor_sync(0xffffffffu, x, j);
    bool i_lt = ((i & j) == 0);
    bool up   = ((i & k) == 0);
    x = (i_lt == up) ? fminf(x, pv) : fmaxf(x, pv);
}

__global__ __launch_bounds__(256)
void attn_kernel(const float* __restrict__ q, const float* __restrict__ k,
                 const float* __restrict__ v, const float* __restrict__ imp,
                 const float* __restrict__ temps, float* __restrict__ out)
{
    __shared__ float q_sT[DHEAD][QB];          // transposed queries, 8 KB
    __shared__ ull   kT2[DHEAD][CHUNK / 2];    // key pairs (j, j+32), 16 KB
    __shared__ float v_s[CHUNK][DHEAD];        // 16 KB
    __shared__ float fac_s[QB];

    const int b  = blockIdx.z;
    const int h  = blockIdx.y;
    const int t0 = blockIdx.x * QB;
    const int tid  = threadIdx.x;
    const int lane = tid & 31;
    const int wid  = tid >> 5;

    // per-query score factor: SCALE / clip(temp) * sigmoid((sigmoid(imp)-0.5)*10)
    if (tid < QB) {
        float tmp = temps[b * HEADS + h];
        tmp = fminf(fmaxf(tmp, 0.1f), 100.f);
        float is = imp[((size_t)b * SEQ + (t0 + tid)) * HEADS + h];
        float ip = 1.f / (1.f + expf(-is));
        float mw = 1.f / (1.f + expf(-((ip - 0.5f) * 10.f)));
        fac_s[tid] = (SCALEF / tmp) * mw;
    }

    // load 32 queries (transposed: q_sT[d][query])
    for (int i = tid; i < QB * DHEAD / 4; i += 256) {
        int qq = i / (DHEAD / 4);
        int dd = (i % (DHEAD / 4)) * 4;
        float4 qv = *(const float4*)&q[((size_t)b * SEQ + (t0 + qq)) * CDIM + h * DHEAD + dd];
        q_sT[dd + 0][qq] = qv.x;
        q_sT[dd + 1][qq] = qv.y;
        q_sT[dd + 2][qq] = qv.z;
        q_sT[dd + 3][qq] = qv.w;
    }

    ull acc01x = 0, acc01y = 0, acc23x = 0, acc23y = 0;  // (q-pair) x (dim)
    const int d0 = lane * 2;
    const int qbase = wid * 4;

    for (int ck = 0; ck < NCHUNK; ck++) {
        __syncthreads();   // protects q_sT/fac_s on first iter, tile reuse after
        const int kt0 = ck * CHUNK;
        for (int i = tid; i < CHUNK * DHEAD / 4; i += 256) {
            int j  = i / (DHEAD / 4);
            int dd = (i % (DHEAD / 4)) * 4;
            size_t gidx = ((size_t)b * SEQ + (kt0 + j)) * CDIM + h * DHEAD + dd;
            float4 kv = *(const float4*)&k[gidx];
            const int slot = j & 31, half = j >> 5;
            ((float*)&kT2[dd + 0][slot])[half] = kv.x;
            ((float*)&kT2[dd + 1][slot])[half] = kv.y;
            ((float*)&kT2[dd + 2][slot])[half] = kv.z;
            ((float*)&kT2[dd + 3][slot])[half] = kv.w;
            *(float4*)&v_s[j][dd] = *(const float4*)&v[gidx];
        }
        __syncthreads();

        // scores: s{0,1}_{01,23} packed across query pairs; lane owns keys lane, lane+32
        ull s0_01 = 0, s0_23 = 0, s1_01 = 0, s1_23 = 0;
#pragma unroll 8
        for (int d = 0; d < DHEAD; d++) {
            ull kp = kT2[d][lane];
            float k0v = lo2(kp), k1v = hi2(kp);
            ull k0d = pack2(k0v, k0v), k1d = pack2(k1v, k1v);
            ull q01 = *(const ull*)&q_sT[d][qbase];
            ull q23 = *(const ull*)&q_sT[d][qbase + 2];
            s0_01 = ffma2(q01, k0d, s0_01);
            s0_23 = ffma2(q23, k0d, s0_23);
            s1_01 = ffma2(q01, k1d, s1_01);
            s1_23 = ffma2(q23, k1d, s1_23);
        }

        float s0[4] = { lo2(s0_01), hi2(s0_01), lo2(s0_23), hi2(s0_23) };
        float s1[4] = { lo2(s1_01), hi2(s1_01), lo2(s1_23), hi2(s1_23) };
        float p0[4], p1[4];

#pragma unroll
        for (int qi = 0; qi < 4; qi++) {
            float f  = fac_s[qbase + qi];
            float a0 = s0[qi] * f;
            float a1 = s1[qi] * f;

            // exact 32nd-largest of 64: warp bitonic full sort (ascending),
            // threshold is sorted index 32 (= x1 of lane 0 after sort)
            float x0 = a0, x1 = a1;           // x0: index lane, x1: index lane+32
#pragma unroll
            for (int kk = 2; kk <= 32; kk <<= 1) {
#pragma unroll
                for (int j = kk >> 1; j > 0; j >>= 1) {
                    bcas(x0, lane, j, kk);
                    bcas(x1, lane + 32, j, kk);
                }
            }
            { float tlo = fminf(x0, x1), thi = fmaxf(x0, x1); x0 = tlo; x1 = thi; }
#pragma unroll
            for (int j = 16; j > 0; j >>= 1) {
                bcas(x0, lane, j, 64);
                bcas(x1, lane + 32, j, 64);
            }
            float thr = __shfl_sync(0xffffffffu, x1, 0);

            float m0 = (a0 >= thr) ? a0 : 0.f;
            float m1 = (a1 >= thr) ? a1 : 0.f;
            float mx = fmaxf(m0, m1);
#pragma unroll
            for (int o = 16; o; o >>= 1)
                mx = fmaxf(mx, __shfl_xor_sync(0xffffffffu, mx, o));
            float e0 = __expf(m0 - mx);
            float e1 = __expf(m1 - mx);
            float ds = e0 + e1;
#pragma unroll
            for (int o = 16; o; o >>= 1)
                ds += __shfl_xor_sync(0xffffffffu, ds, o);
            float inv = 1.f / ds;
            p0[qi] = e0 * inv;
            p1[qi] = e1 * inv;
        }

        // p @ v: shfl-broadcast p, packed f32x2 across query pairs
#pragma unroll 8
        for (int j = 0; j < 32; j++) {
            float2 vv = *(const float2*)&v_s[j][d0];
            ull vxd = pack2(vv.x, vv.x), vyd = pack2(vv.y, vv.y);
            ull pp01 = pack2(__shfl_sync(0xffffffffu, p0[0], j),
                             __shfl_sync(0xffffffffu, p0[1], j));
            ull pp23 = pack2(__shfl_sync(0xffffffffu, p0[2], j),
                             __shfl_sync(0xffffffffu, p0[3], j));
            acc01x = ffma2(pp01, vxd, acc01x);
            acc01y = ffma2(pp01, vyd, acc01y);
            acc23x = ffma2(pp23, vxd, acc23x);
            acc23y = ffma2(pp23, vyd, acc23y);
        }
#pragma unroll 8
        for (int j = 0; j < 32; j++) {
            float2 vv = *(const float2*)&v_s[j + 32][d0];
            ull vxd = pack2(vv.x, vv.x), vyd = pack2(vv.y, vv.y);
            ull pp01 = pack2(__shfl_sync(0xffffffffu, p1[0], j),
                             __shfl_sync(0xffffffffu, p1[1], j));
            ull pp23 = pack2(__shfl_sync(0xffffffffu, p1[2], j),
                             __shfl_sync(0xffffffffu, p1[3], j));
            acc01x = ffma2(pp01, vxd, acc01x);
            acc01y = ffma2(pp01, vyd, acc01y);
            acc23x = ffma2(pp23, vxd, acc23x);
            acc23y = ffma2(pp23, vyd, acc23y);
        }
    }

    // write [B,T,C]; normalizer sum(p) == NCHUNK == 16 exactly
    const float invn = 1.f / 16.f;
    float ox[4] = { lo2(acc01x), hi2(acc01x), lo2(acc23x), hi2(acc23x) };
    float oy[4] = { lo2(acc01y), hi2(acc01y), lo2(acc23y), hi2(acc23y) };
#pragma unroll
    for (int qi = 0; qi < 4; qi++) {
        int ql = qbase + qi;
        float2 o2 = make_float2(ox[qi] * invn, oy[qi] * invn);
        *(float2*)&out[((size_t)b * SEQ + (t0 + ql)) * CDIM + h * DHEAD + d0] = o2;
    }
}

// ---------------------------------------------------------------------------
// Launch
// ---------------------------------------------------------------------------
extern "C" void kernel_launch(void* const* d_in, const int* in_sizes, int n_in,
                              void* d_out, int out_size)
{
    const float* x    = (const float*)d_in[0];
    const float* impS = (const float*)d_in[1];
    const float* temp = (const float*)d_in[2];
    const float* Wq   = (const float*)d_in[3];
    const float* Wk   = (const float*)d_in[4];
    const float* Wv   = (const float*)d_in[5];
    const float* Wo   = (const float*)d_in[6];
    float* outp = (float*)d_out;

    float *pq, *pk, *pv, *pa;
    cudaGetSymbolAddress((void**)&pq, g_q);
    cudaGetSymbolAddress((void**)&pk, g_k);
    cudaGetSymbolAddress((void**)&pv, g_v);
    cudaGetSymbolAddress((void**)&pa, g_attn);

    const int M = BATCH * SEQ;   // 4096
    const int N = CDIM;          // 1024
    const int K = CDIM;          // 1024
    dim3 ggrid(N / GBN, M / GBM);

    sgemm_kernel<<<ggrid, 256>>>(x, Wq, pq, M, N, K);
    sgemm_kernel<<<ggrid, 256>>>(x, Wk, pk, M, N, K);
    sgemm_kernel<<<ggrid, 256>>>(x, Wv, pv, M, N, K);

    dim3 agrid(SEQ / QB, HEADS, BATCH);
    attn_kernel<<<agrid, 256>>>(pq, pk, pv, impS, temp, pa);

    sgemm_kernel<<<ggrid, 256>>>(pa, Wo, outp, M, N, K);
}